// round 1
// baseline (speedup 1.0000x reference)
#include <cuda_runtime.h>

#define BB 64
#define HH 56
#define WW 56
#define CC 256
#define COUT 64
#define ROUTES 4
#define RW (CC / ROUTES)          // 64 channels per route
#define SSZ (BB * 9 * CC)         // partial patch sums

__device__ float g_S[SSZ];
__device__ int   g_route[BB];

// ---------------------------------------------------------------------------
// Zero the accumulator (graph replays re-run this every launch)
// ---------------------------------------------------------------------------
__global__ void zero_S_kernel() {
    int i = blockIdx.x * blockDim.x + threadIdx.x;
    if (i < SSZ) g_S[i] = 0.f;
}

// ---------------------------------------------------------------------------
// K1: streaming reduction. S[b][dh][dw][c] = sum over strided conv-window
// positions. One block = (batch b, 8-row chunk), thread = channel c.
// Per row: evenSum/oddSum + 3 edge corrections give the three w-class sums.
// ---------------------------------------------------------------------------
__global__ void patch_sums_kernel(const float* __restrict__ in) {
    const int b     = blockIdx.x;
    const int chunk = blockIdx.y;
    const int c     = threadIdx.x;

    const float* base = in + (size_t)b * HH * WW * CC + c;

    float acc[3][3];
#pragma unroll
    for (int i = 0; i < 3; i++)
#pragma unroll
        for (int j = 0; j < 3; j++) acc[i][j] = 0.f;

#pragma unroll
    for (int r = 0; r < 8; r++) {
        const int h = chunk * 8 + r;
        const float* row = base + (size_t)h * WW * CC;

        float e = 0.f, o = 0.f, v0 = 0.f, v54 = 0.f, v55 = 0.f;
#pragma unroll
        for (int w = 0; w < WW; w += 2) {
            float a  = row[(size_t)w * CC];
            float bb = row[(size_t)(w + 1) * CC];
            e += a;
            o += bb;
            if (w == 0)  { v0 = a; }
            if (w == 54) { v54 = a; v55 = bb; }
        }
        // w-class sums: dw=0 -> even w in [0,52]; dw=1 -> odd w in [1,53]; dw=2 -> even w in [2,54]
        const float W0 = e - v54;
        const float W1 = o - v55;
        const float W2 = e - v0;

        if ((h & 1) == 0) {
            if (h <= 52) { acc[0][0] += W0; acc[0][1] += W1; acc[0][2] += W2; }
            if (h >= 2)  { acc[2][0] += W0; acc[2][1] += W1; acc[2][2] += W2; }
        } else {
            if (h <= 53) { acc[1][0] += W0; acc[1][1] += W1; acc[1][2] += W2; }
        }
    }

    float* Sb = g_S + (size_t)b * 9 * CC + c;
#pragma unroll
    for (int dh = 0; dh < 3; dh++)
#pragma unroll
        for (int dw = 0; dw < 3; dw++)
            atomicAdd(Sb + (dh * 3 + dw) * CC, acc[dh][dw]);
}

// ---------------------------------------------------------------------------
// K2: tiny GEMM (2304 x 64 per batch) + dense(4) + argmax. One block / batch.
// ---------------------------------------------------------------------------
__global__ void logits_route_kernel(const float* __restrict__ conv_w,
                                    const float* __restrict__ conv_b,
                                    const float* __restrict__ fc_w,
                                    const float* __restrict__ fc_b,
                                    float* __restrict__ out_logits) {
    const int b = blockIdx.x;
    const int o = threadIdx.x;  // 0..63

    __shared__ float sS[9 * CC];
    for (int i = o; i < 9 * CC; i += COUT)
        sS[i] = g_S[(size_t)b * 9 * CC + i];
    __syncthreads();

    float acc = 0.f;
#pragma unroll 8
    for (int i = 0; i < 9 * CC; i++)
        acc = fmaf(sS[i], conv_w[(size_t)i * COUT + o], acc);

    const float pooled = acc * (1.0f / 729.0f) + conv_b[o];

    __shared__ float sp[COUT];
    sp[o] = pooled;
    __syncthreads();

    __shared__ float slog[ROUTES];
    if (o < ROUTES) {
        float l = fc_b[o];
#pragma unroll
        for (int j = 0; j < COUT; j++)
            l = fmaf(sp[j], fc_w[j * ROUTES + o], l);
        slog[o] = l;
        out_logits[b * ROUTES + o] = l;
    }
    __syncthreads();

    if (o == 0) {
        float best = slog[0];
        int br = 0;
#pragma unroll
        for (int r = 1; r < ROUTES; r++)
            if (slog[r] > best) { best = slog[r]; br = r; }  // first-max, matches argmax
        g_route[b] = br;
    }
}

// ---------------------------------------------------------------------------
// K3: routed channel-group gather, vectorized float4.
// out[b,h,w,j] = in[b,h,w, route[b]*64 + j]
// ---------------------------------------------------------------------------
__global__ void gather_kernel(const float4* __restrict__ in4,
                              float4* __restrict__ out4) {
    const int idx = blockIdx.x * blockDim.x + threadIdx.x;  // BB*3136*16 total
    const int pix = idx >> 4;        // which (b,h,w)
    const int j   = idx & 15;        // which float4 within the 64-ch group
    const int b   = pix / (HH * WW);
    const int r   = g_route[b];
    out4[idx] = in4[(size_t)pix * (CC / 4) + r * (RW / 4) + j];
}

// ---------------------------------------------------------------------------
extern "C" void kernel_launch(void* const* d_in, const int* in_sizes, int n_in,
                              void* d_out, int out_size) {
    const float* in     = (const float*)d_in[0];
    const float* conv_w = (const float*)d_in[1];
    const float* conv_b = (const float*)d_in[2];
    const float* fc_w   = (const float*)d_in[3];
    const float* fc_b   = (const float*)d_in[4];

    float* out        = (float*)d_out;
    float* out_logits = out + (size_t)BB * HH * WW * RW;  // x first, then logits

    zero_S_kernel<<<(SSZ + 255) / 256, 256>>>();
    patch_sums_kernel<<<dim3(BB, 7), 256>>>(in);
    logits_route_kernel<<<BB, COUT>>>(conv_w, conv_b, fc_w, fc_b, out_logits);

    const int total4 = BB * HH * WW * (RW / 4);  // 3,211,264
    gather_kernel<<<total4 / 256, 256>>>((const float4*)in, (float4*)out);
}

// round 2
// speedup vs baseline: 1.9747x; 1.9747x over previous
#include <cuda_runtime.h>

#define BB 64
#define HH 56
#define WW 56
#define CC 256
#define COUT 64
#define ROUTES 4
#define RW (CC / ROUTES)          // 64 channels per route
#define CHUNKS 7                  // 8 rows per chunk
#define SLOTS 9                   // 3x3 (dh,dw) classes

// per-(batch,chunk) partial patch sums: [BB][CHUNKS][SLOTS][CC] floats (~4 MB)
__device__ float g_S2[BB * CHUNKS * SLOTS * CC];
__device__ int   g_route[BB];

__device__ __forceinline__ float4 f4add(float4 a, float4 b) {
    return make_float4(a.x + b.x, a.y + b.y, a.z + b.z, a.w + b.w);
}
__device__ __forceinline__ float4 f4sub(float4 a, float4 b) {
    return make_float4(a.x - b.x, a.y - b.y, a.z - b.z, a.w - b.w);
}

// ---------------------------------------------------------------------------
// K1: streaming patch-sum reduction, float4, atomic-free.
// Block = (batch b, 8-row chunk). 256 threads = 64 channel-quads x 4 row-threads.
// Each row-thread handles 2 rows. Per row: even/odd running sums + 3 edge
// corrections give the three dw-class sums; parity of h selects dh classes.
// ---------------------------------------------------------------------------
__global__ __launch_bounds__(256) void patch_sums_kernel(const float* __restrict__ in) {
    const int b     = blockIdx.x;
    const int chunk = blockIdx.y;
    const int q     = threadIdx.x & 63;   // channel quad 0..63
    const int rt    = threadIdx.x >> 6;   // row-thread 0..3

    const float4* base = (const float4*)in + (size_t)b * HH * WW * (CC / 4) + q;

    float4 acc[3][3];
#pragma unroll
    for (int i = 0; i < 3; i++)
#pragma unroll
        for (int j = 0; j < 3; j++) acc[i][j] = make_float4(0.f, 0.f, 0.f, 0.f);

#pragma unroll
    for (int rr = 0; rr < 2; rr++) {
        const int h = chunk * 8 + rt * 2 + rr;
        const float4* row = base + (size_t)h * WW * (CC / 4);

        float4 e = make_float4(0.f, 0.f, 0.f, 0.f);
        float4 o = make_float4(0.f, 0.f, 0.f, 0.f);
#pragma unroll 7
        for (int w = 0; w < WW; w += 2) {
            e = f4add(e, row[(size_t)w * (CC / 4)]);
            o = f4add(o, row[(size_t)(w + 1) * (CC / 4)]);
        }
        // edges re-load from L1 (just touched)
        const float4 v0  = row[0];
        const float4 v54 = row[(size_t)54 * (CC / 4)];
        const float4 v55 = row[(size_t)55 * (CC / 4)];

        const float4 W0 = f4sub(e, v54);  // even w in [0,52]
        const float4 W1 = f4sub(o, v55);  // odd  w in [1,53]
        const float4 W2 = f4sub(e, v0);   // even w in [2,54]

        if ((h & 1) == 0) {
            if (h <= 52) { acc[0][0] = f4add(acc[0][0], W0); acc[0][1] = f4add(acc[0][1], W1); acc[0][2] = f4add(acc[0][2], W2); }
            if (h >= 2)  { acc[2][0] = f4add(acc[2][0], W0); acc[2][1] = f4add(acc[2][1], W1); acc[2][2] = f4add(acc[2][2], W2); }
        } else {
            if (h <= 53) { acc[1][0] = f4add(acc[1][0], W0); acc[1][1] = f4add(acc[1][1], W1); acc[1][2] = f4add(acc[1][2], W2); }
        }
    }

    __shared__ float4 sacc[4][SLOTS][64];
#pragma unroll
    for (int dh = 0; dh < 3; dh++)
#pragma unroll
        for (int dw = 0; dw < 3; dw++)
            sacc[rt][dh * 3 + dw][q] = acc[dh][dw];
    __syncthreads();

    if (rt == 0) {
        float4* dst = (float4*)g_S2 + ((size_t)(b * CHUNKS + chunk) * SLOTS) * (CC / 4) + q;
#pragma unroll
        for (int s = 0; s < SLOTS; s++) {
            float4 r = f4add(f4add(sacc[0][s][q], sacc[1][s][q]),
                             f4add(sacc[2][s][q], sacc[3][s][q]));
            dst[(size_t)s * (CC / 4)] = r;
        }
    }
}

// ---------------------------------------------------------------------------
// K2: per-batch: sum 7 chunk-partials -> S (9*256), tiny GEMM to pooled(64),
// dense(4) + argmax. 256 threads: 4 i-segments x 64 outputs.
// ---------------------------------------------------------------------------
__global__ __launch_bounds__(256) void logits_route_kernel(const float* __restrict__ conv_w,
                                                           const float* __restrict__ conv_b,
                                                           const float* __restrict__ fc_w,
                                                           const float* __restrict__ fc_b,
                                                           float* __restrict__ out_logits) {
    const int b   = blockIdx.x;
    const int tid = threadIdx.x;
    const int o   = tid & 63;
    const int seg = tid >> 6;          // 0..3

    __shared__ float sS[SLOTS * CC];   // 2304
    for (int i = tid; i < SLOTS * CC; i += 256) {
        float s = 0.f;
#pragma unroll
        for (int k = 0; k < CHUNKS; k++)
            s += g_S2[((size_t)(b * CHUNKS + k) * SLOTS * CC) + i];
        sS[i] = s;
    }
    __syncthreads();

    float acc = 0.f;
    const int i0 = seg * (SLOTS * CC / 4);   // 576 per segment
#pragma unroll 8
    for (int i = 0; i < SLOTS * CC / 4; i++)
        acc = fmaf(sS[i0 + i], conv_w[(size_t)(i0 + i) * COUT + o], acc);

    __shared__ float part[4][COUT];
    part[seg][o] = acc;
    __syncthreads();

    __shared__ float sp[COUT];
    __shared__ float slog[ROUTES];
    if (tid < COUT) {
        float pooled = (part[0][o] + part[1][o] + part[2][o] + part[3][o]) * (1.0f / 729.0f)
                       + conv_b[o];
        sp[o] = pooled;
    }
    __syncthreads();

    if (tid < ROUTES) {
        float l = fc_b[tid];
#pragma unroll
        for (int j = 0; j < COUT; j++)
            l = fmaf(sp[j], fc_w[j * ROUTES + tid], l);
        slog[tid] = l;
        out_logits[b * ROUTES + tid] = l;
    }
    __syncthreads();

    if (tid == 0) {
        float best = slog[0];
        int br = 0;
#pragma unroll
        for (int r = 1; r < ROUTES; r++)
            if (slog[r] > best) { best = slog[r]; br = r; }  // first-max == argmax
        g_route[b] = br;
    }
}

// ---------------------------------------------------------------------------
// K3: routed channel-group gather. Block = (batch, 64-pixel tile), route read
// once per block, 4 independent float4 copies per thread, no divisions.
// ---------------------------------------------------------------------------
__global__ __launch_bounds__(256) void gather_kernel(const float4* __restrict__ in4,
                                                     float4* __restrict__ out4) {
    const int b = blockIdx.x;
    const int r = g_route[b];
    const size_t base_pix = (size_t)b * (HH * WW) + blockIdx.y * 64;
    const float4* src = in4 + base_pix * (CC / 4) + r * (RW / 4);
    float4* dst = out4 + base_pix * (RW / 4);

    const int t = threadIdx.x;
#pragma unroll
    for (int k = 0; k < 4; k++) {
        const int item = t + k * 256;      // 0..1023 = 64 pixels x 16 float4
        const int p = item >> 4;
        const int j = item & 15;
        dst[item] = src[(size_t)p * (CC / 4) + j];
    }
}

// ---------------------------------------------------------------------------
extern "C" void kernel_launch(void* const* d_in, const int* in_sizes, int n_in,
                              void* d_out, int out_size) {
    const float* in     = (const float*)d_in[0];
    const float* conv_w = (const float*)d_in[1];
    const float* conv_b = (const float*)d_in[2];
    const float* fc_w   = (const float*)d_in[3];
    const float* fc_b   = (const float*)d_in[4];

    float* out        = (float*)d_out;
    float* out_logits = out + (size_t)BB * HH * WW * RW;  // x first, then logits

    patch_sums_kernel<<<dim3(BB, CHUNKS), 256>>>(in);
    logits_route_kernel<<<BB, 256>>>(conv_w, conv_b, fc_w, fc_b, out_logits);
    gather_kernel<<<dim3(BB, HH * WW / 64), 256>>>((const float4*)in, (float4*)out);
}

// round 3
// speedup vs baseline: 2.6772x; 1.3557x over previous
#include <cuda_runtime.h>

#define BB 64
#define HH 56
#define WW 56
#define CC 256
#define COUT 64
#define ROUTES 4
#define RW (CC / ROUTES)          // 64 channels per route
#define RCHUNKS 14                // 4 rows per chunk
#define SLOTS 9                   // 3x3 (dh,dw) classes

// per-(batch,chunk) partial patch sums: [BB][RCHUNKS][SLOTS][CC] floats (~8 MB)
__device__ float g_S2[BB * RCHUNKS * SLOTS * CC];
// per-(batch,seg) partial pooled GEMM results: [BB][4][COUT]
__device__ float g_part[BB * 4 * COUT];
__device__ int   g_route[BB];

__device__ __forceinline__ float4 f4add(float4 a, float4 b) {
    return make_float4(a.x + b.x, a.y + b.y, a.z + b.z, a.w + b.w);
}
__device__ __forceinline__ float4 f4sub(float4 a, float4 b) {
    return make_float4(a.x - b.x, a.y - b.y, a.z - b.z, a.w - b.w);
}

// ---------------------------------------------------------------------------
// K1: streaming patch-sum reduction. Block = (batch, 4-row chunk).
// 256 threads = 64 channel-quads x 4 row-threads; each row-thread owns ONE row.
// Per row: even/odd running sums + edge captures give the three dw-class sums
// (W0,W1,W2). Reducer thread (rt==0) applies h-parity/boundary logic in smem.
// ---------------------------------------------------------------------------
__global__ __launch_bounds__(256) void patch_sums_kernel(const float* __restrict__ in) {
    const int b     = blockIdx.x;
    const int chunk = blockIdx.y;
    const int q     = threadIdx.x & 63;   // channel quad 0..63
    const int rt    = threadIdx.x >> 6;   // row-thread 0..3
    const int h     = chunk * 4 + rt;

    const float4* row = (const float4*)in
                      + ((size_t)(b * HH + h) * WW) * (CC / 4) + q;

    float4 e = make_float4(0.f, 0.f, 0.f, 0.f);
    float4 o = make_float4(0.f, 0.f, 0.f, 0.f);
    float4 v0, v54, v55;
#pragma unroll
    for (int w = 0; w < WW; w += 2) {
        float4 a  = row[(size_t)w * (CC / 4)];
        float4 bb = row[(size_t)(w + 1) * (CC / 4)];
        if (w == 0)  { v0 = a; }
        if (w == 54) { v54 = a; v55 = bb; }
        e = f4add(e, a);
        o = f4add(o, bb);
    }

    __shared__ float4 sacc[4][3][64];
    sacc[rt][0][q] = f4sub(e, v54);  // W0: even w in [0,52]
    sacc[rt][1][q] = f4sub(o, v55);  // W1: odd  w in [1,53]
    sacc[rt][2][q] = f4sub(e, v0);   // W2: even w in [2,54]
    __syncthreads();

    if (rt == 0) {
        float4 out[SLOTS];
#pragma unroll
        for (int s = 0; s < SLOTS; s++) out[s] = make_float4(0.f, 0.f, 0.f, 0.f);

#pragma unroll
        for (int r = 0; r < 4; r++) {
            const int hh = chunk * 4 + r;
            const float4 W0 = sacc[r][0][q];
            const float4 W1 = sacc[r][1][q];
            const float4 W2 = sacc[r][2][q];
            if ((hh & 1) == 0) {
                if (hh <= 52) { out[0] = f4add(out[0], W0); out[1] = f4add(out[1], W1); out[2] = f4add(out[2], W2); }
                if (hh >= 2)  { out[6] = f4add(out[6], W0); out[7] = f4add(out[7], W1); out[8] = f4add(out[8], W2); }
            } else {
                if (hh <= 53) { out[3] = f4add(out[3], W0); out[4] = f4add(out[4], W1); out[5] = f4add(out[5], W2); }
            }
        }

        float4* dst = (float4*)g_S2 + ((size_t)(b * RCHUNKS + chunk) * SLOTS) * (CC / 4) + q;
#pragma unroll
        for (int s = 0; s < SLOTS; s++)
            dst[(size_t)s * (CC / 4)] = out[s];
    }
}

// ---------------------------------------------------------------------------
// K2a: block = (batch, i-segment of 576). Sum 14 chunk-partials for this
// segment, then partial GEMM against conv_w -> g_part[b][seg][o].
// 256 threads = 64 o x 4 sub-segments (144-long fmaf chains).
// ---------------------------------------------------------------------------
__global__ __launch_bounds__(256) void pooled_gemm_kernel(const float* __restrict__ conv_w) {
    const int b   = blockIdx.x;
    const int seg = blockIdx.y;        // 0..3
    const int tid = threadIdx.x;
    const int i0  = seg * 576;

    __shared__ __align__(16) float sS[576];
    if (tid < 144) {
        float4 s = make_float4(0.f, 0.f, 0.f, 0.f);
#pragma unroll
        for (int k = 0; k < RCHUNKS; k++) {
            const float4* src = (const float4*)g_S2
                              + (size_t)(b * RCHUNKS + k) * (SLOTS * CC / 4)
                              + (i0 / 4) + tid;
            s = f4add(s, *src);
        }
        ((float4*)sS)[tid] = s;
    }
    __syncthreads();

    const int o   = tid & 63;
    const int sub = tid >> 6;
    const int j0  = sub * 144;

    float acc = 0.f;
#pragma unroll 8
    for (int j = 0; j < 144; j++)
        acc = fmaf(sS[j0 + j], conv_w[(size_t)(i0 + j0 + j) * COUT + o], acc);

    __shared__ float part[4][COUT];
    part[sub][o] = acc;
    __syncthreads();

    if (tid < COUT)
        g_part[(b * 4 + seg) * COUT + tid] =
            part[0][tid] + part[1][tid] + part[2][tid] + part[3][tid];
}

// ---------------------------------------------------------------------------
// K2b: per-batch finisher. pooled(64) -> dense(4) -> argmax -> route.
// ---------------------------------------------------------------------------
__global__ __launch_bounds__(64) void logits_route_kernel(const float* __restrict__ conv_b,
                                                          const float* __restrict__ fc_w,
                                                          const float* __restrict__ fc_b,
                                                          float* __restrict__ out_logits) {
    const int b = blockIdx.x;
    const int o = threadIdx.x;  // 0..63

    __shared__ float sp[COUT];
    __shared__ float slog[ROUTES];

    const float* p = g_part + b * 4 * COUT;
    sp[o] = (p[o] + p[COUT + o] + p[2 * COUT + o] + p[3 * COUT + o]) * (1.0f / 729.0f)
            + conv_b[o];
    __syncthreads();

    if (o < ROUTES) {
        float l = fc_b[o];
#pragma unroll
        for (int j = 0; j < COUT; j++)
            l = fmaf(sp[j], fc_w[j * ROUTES + o], l);
        slog[o] = l;
        out_logits[b * ROUTES + o] = l;
    }
    __syncthreads();

    if (o == 0) {
        float best = slog[0];
        int br = 0;
#pragma unroll
        for (int r = 1; r < ROUTES; r++)
            if (slog[r] > best) { best = slog[r]; br = r; }  // first-max == argmax
        g_route[b] = br;
    }
}

// ---------------------------------------------------------------------------
// K3: routed channel-group gather. Block = (batch, 64-pixel tile).
// ---------------------------------------------------------------------------
__global__ __launch_bounds__(256) void gather_kernel(const float4* __restrict__ in4,
                                                     float4* __restrict__ out4) {
    const int b = blockIdx.x;
    const int r = g_route[b];
    const size_t base_pix = (size_t)b * (HH * WW) + blockIdx.y * 64;
    const float4* src = in4 + base_pix * (CC / 4) + r * (RW / 4);
    float4* dst = out4 + base_pix * (RW / 4);

    const int t = threadIdx.x;
#pragma unroll
    for (int k = 0; k < 4; k++) {
        const int item = t + k * 256;      // 0..1023 = 64 pixels x 16 float4
        const int p = item >> 4;
        const int j = item & 15;
        dst[item] = src[(size_t)p * (CC / 4) + j];
    }
}

// ---------------------------------------------------------------------------
extern "C" void kernel_launch(void* const* d_in, const int* in_sizes, int n_in,
                              void* d_out, int out_size) {
    const float* in     = (const float*)d_in[0];
    const float* conv_w = (const float*)d_in[1];
    const float* conv_b = (const float*)d_in[2];
    const float* fc_w   = (const float*)d_in[3];
    const float* fc_b   = (const float*)d_in[4];

    float* out        = (float*)d_out;
    float* out_logits = out + (size_t)BB * HH * WW * RW;  // x first, then logits

    patch_sums_kernel<<<dim3(BB, RCHUNKS), 256>>>(in);
    pooled_gemm_kernel<<<dim3(BB, 4), 256>>>(conv_w);
    logits_route_kernel<<<BB, 64>>>(conv_b, fc_w, fc_b, out_logits);
    gather_kernel<<<dim3(BB, HH * WW / 64), 256>>>((const float4*)in, (float4*)out);
}